// round 2
// baseline (speedup 1.0000x reference)
#include <cuda_runtime.h>
#include <math.h>

// Problem constants (fixed by the reference: T=1024, B=32, I=H=512)
#define T_STEPS 1024
#define BATCH   32
#define HID     512
#define INP     512
#define G4      2048        // 4*HID
#define NCTA    128         // persistent CTAs for recurrence (1/SM, all resident)
#define TPB     256

// Output layout: (output[T,B,H], h_T[1,B,H], c_T[1,B,H], all_hidden[T,B,H])
#define OFF_HT  ((size_t)T_STEPS * BATCH * HID)                 // 16777216
#define OFF_CT  (OFF_HT + (size_t)BATCH * HID)                  // 16793600
#define OFF_ALL (OFF_CT + (size_t)BATCH * HID)                  // 16809984

// Scratch: precomputed x@Wx^T + b for all timesteps (256 MB, static device mem)
__device__ float g_xp[(size_t)T_STEPS * BATCH * G4];
// Double-buffered hidden state broadcast between CTAs
__device__ float g_h[2][BATCH * HID];
// Grid barrier state (self-resetting across graph replays)
__device__ unsigned g_count = 0;
__device__ volatile unsigned g_sense = 0;

// ---------------------------------------------------------------------------
// Phase 1: XP[m][n] = X[m][:] . Wx[n][:] + bias[n],  M=32768, N=2048, K=512
// 64(M) x 128(N) tile, 256 threads, 4x8 register blocking, K-tile 16.
// Software-prefetched: next K-tile's global loads issue BEFORE the FFMA block,
// hiding ~600cyc load latency under ~1000cyc of compute.
// ---------------------------------------------------------------------------
__global__ void __launch_bounds__(256, 2) pregemm_kernel(
    const float* __restrict__ X,
    const float* __restrict__ Wx,
    const float* __restrict__ bias)
{
    __shared__ float As[16][68];    // [k][m], pad 4
    __shared__ float Bs[16][132];   // [k][n]

    const int t  = threadIdx.x;
    const int m0 = blockIdx.y * 64;
    const int n0 = blockIdx.x * 128;
    const int tm = (t >> 4) << 2;   // 0..60
    const int tn = (t & 15) << 3;   // 0..120
    const int lr = t >> 2;          // 0..63
    const int lk = (t & 3) << 2;    // 0,4,8,12

    float acc[4][8];
#pragma unroll
    for (int i = 0; i < 4; i++)
#pragma unroll
        for (int j = 0; j < 8; j++) acc[i][j] = 0.f;

    const float* Arow  = X  + (size_t)(m0 + lr) * INP + lk;
    const float* Brow0 = Wx + (size_t)(n0 + lr) * INP + lk;
    const float* Brow1 = Wx + (size_t)(n0 + 64 + lr) * INP + lk;

    // Prefetch tile 0
    float4 av = *(const float4*)(Arow);
    float4 b0 = *(const float4*)(Brow0);
    float4 b1 = *(const float4*)(Brow1);

    for (int kt = 0; kt < INP; kt += 16) {
        __syncthreads();
        As[lk + 0][lr] = av.x; As[lk + 1][lr] = av.y;
        As[lk + 2][lr] = av.z; As[lk + 3][lr] = av.w;
        Bs[lk + 0][lr] = b0.x; Bs[lk + 1][lr] = b0.y;
        Bs[lk + 2][lr] = b0.z; Bs[lk + 3][lr] = b0.w;
        Bs[lk + 0][64 + lr] = b1.x; Bs[lk + 1][64 + lr] = b1.y;
        Bs[lk + 2][64 + lr] = b1.z; Bs[lk + 3][64 + lr] = b1.w;
        __syncthreads();

        // Issue next tile's loads now; latency hides under the FFMA block.
        if (kt + 16 < INP) {
            av = *(const float4*)(Arow  + kt + 16);
            b0 = *(const float4*)(Brow0 + kt + 16);
            b1 = *(const float4*)(Brow1 + kt + 16);
        }

#pragma unroll
        for (int k = 0; k < 16; k++) {
            float4 a = *(const float4*)&As[k][tm];
            float4 p = *(const float4*)&Bs[k][tn];
            float4 q = *(const float4*)&Bs[k][tn + 4];
            float ar[4] = {a.x, a.y, a.z, a.w};
            float br[8] = {p.x, p.y, p.z, p.w, q.x, q.y, q.z, q.w};
#pragma unroll
            for (int i = 0; i < 4; i++)
#pragma unroll
                for (int j = 0; j < 8; j++) acc[i][j] += ar[i] * br[j];
        }
    }

    float bl[8];
#pragma unroll
    for (int j = 0; j < 8; j++) bl[j] = bias[n0 + tn + j];
#pragma unroll
    for (int i = 0; i < 4; i++) {
        float4 s0 = make_float4(acc[i][0] + bl[0], acc[i][1] + bl[1],
                                acc[i][2] + bl[2], acc[i][3] + bl[3]);
        float4 s1 = make_float4(acc[i][4] + bl[4], acc[i][5] + bl[5],
                                acc[i][6] + bl[6], acc[i][7] + bl[7]);
        float* dst = g_xp + (size_t)(m0 + tm + i) * G4 + n0 + tn;
        *(float4*)dst       = s0;
        *(float4*)(dst + 4) = s1;
    }
}

// ---------------------------------------------------------------------------
// Phase 2: persistent recurrent kernel. 128 CTAs x 256 threads, 1 CTA/SM.
// CTA owns 4 hidden units (16 gate rows of Wh, SMEM-resident).
// Warp w: col-group (w&3) of 4 gate cols, k-half (w>>2). Lane = batch.
// Grid barrier once per step; h double-buffered in global (L2-coherent).
// ---------------------------------------------------------------------------
__device__ __forceinline__ float sigmoidf_(float x) {
    return 1.f / (1.f + expf(-x));
}

__device__ __forceinline__ void grid_barrier(unsigned& lsense) {
    __syncthreads();
    if (threadIdx.x == 0) {
        __threadfence();
        unsigned s = lsense ^ 1u;
        lsense = s;
        if (atomicAdd(&g_count, 1u) == (unsigned)(gridDim.x - 1)) {
            atomicExch(&g_count, 0u);   // reset before release
            __threadfence();
            g_sense = s;                // release
        } else {
            while (g_sense != s) __nanosleep(32);
        }
        __threadfence();                // acquire
    }
    __syncthreads();
}

// SMEM layout (floats): hs[32][516] | ws[16][512] | part[2][32][21]
#define HS_STRIDE 516
#define SM_HS     0
#define SM_WS     (32 * HS_STRIDE)              // 16512
#define SM_PART   (SM_WS + 16 * 512)            // 24704
#define PART_STR  21
#define SM_TOTALF (SM_PART + 2 * 32 * PART_STR) // 26048
#define SMEM_BYTES (SM_TOTALF * 4)              // 104192 B

__global__ void __launch_bounds__(256, 1) lstm_kernel(
    const float* __restrict__ Wh,
    const float* __restrict__ h0,
    const float* __restrict__ c0,
    float* __restrict__ out)
{
    extern __shared__ __align__(16) float sm[];
    float* hs   = sm + SM_HS;
    float* ws   = sm + SM_WS;
    float* part = sm + SM_PART;

    const int t  = threadIdx.x;
    const int u0 = blockIdx.x * 4;          // first owned hidden unit

    // Load this CTA's 16 Wh rows into SMEM, layout ws[unit*4+gate][k].
    // Gate order q: 0=i,1=f,2=g,3=o; Wh row = q*HID + (u0+unit).
#pragma unroll
    for (int i = 0; i < 8; i++) {
        int j  = t + i * 256;               // 0..2047 float4s
        int lc = j >> 7;                    // local col 0..15
        int kf = j & 127;
        int ul = lc >> 2, q = lc & 3;
        float4 v = *(const float4*)(Wh + (size_t)(q * HID + u0 + ul) * HID + kf * 4);
        *(float4*)(ws + lc * 512 + kf * 4) = v;
    }

    unsigned lsense = g_sense;              // consistent snapshot (no writers yet)

    // Elementwise thread mapping (t < 128): eb = batch, eu = local unit
    const int eb = t >> 2;
    const int eu = t & 3;
    float cc = 0.f, hh = 0.f;
    if (t < 128) {
        cc = c0[eb * HID + u0 + eu];
        hh = h0[eb * HID + u0 + eu];
        g_h[0][eb * HID + u0 + eu] = hh;
    }

    grid_barrier(lsense);                   // h0 visible everywhere

    const int lane = t & 31;
    const int wid  = t >> 5;
    const int cg   = wid & 3;               // column group (= owned unit index)
    const int kh   = wid >> 2;              // k half
    const float4* ws4 = (const float4*)ws;
    float4*       hs4 = (float4*)hs;

    const float4* wp0 = ws4 + (cg * 4 + 0) * 128 + kh * 64;
    const float4* wp1 = ws4 + (cg * 4 + 1) * 128 + kh * 64;
    const float4* wp2 = ws4 + (cg * 4 + 2) * 128 + kh * 64;
    const float4* wp3 = ws4 + (cg * 4 + 3) * 128 + kh * 64;
    float4* hp = hs4 + lane * 129 + kh * 64;

    for (int ts = 0; ts < T_STEPS; ts++) {
        // Prefetch x-part of gates for this step (hidden by h load + compute)
        float xq0 = 0.f, xq1 = 0.f, xq2 = 0.f, xq3 = 0.f;
        if (t < 128) {
            const float* xp = g_xp + ((size_t)ts * BATCH + eb) * G4 + (u0 + eu);
            xq0 = __ldg(xp);
            xq1 = __ldg(xp + 512);
            xq2 = __ldg(xp + 1024);
            xq3 = __ldg(xp + 1536);
        }

        // Cooperative load of h (64 KB) into padded SMEM, L2-coherent reads
        const float4* hsrc = (const float4*)g_h[ts & 1];
#pragma unroll
        for (int i = 0; i < 16; i++) {
            int j  = t + i * 256;           // 0..4095
            int b  = j >> 7;
            int k4 = j & 127;
            hs4[b * 129 + k4] = __ldcg(hsrc + j);
        }
        __syncthreads();

        // 4 gate-col dot products over this warp's k-half (256 elements)
        float a0 = 0.f, a1 = 0.f, a2 = 0.f, a3 = 0.f;
#pragma unroll 4
        for (int k = 0; k < 64; k++) {
            float4 hv = hp[k];
            float4 w0 = wp0[k], w1 = wp1[k], w2 = wp2[k], w3 = wp3[k];
            a0 += hv.x * w0.x + hv.y * w0.y + hv.z * w0.z + hv.w * w0.w;
            a1 += hv.x * w1.x + hv.y * w1.y + hv.z * w1.z + hv.w * w1.w;
            a2 += hv.x * w2.x + hv.y * w2.y + hv.z * w2.z + hv.w * w2.w;
            a3 += hv.x * w3.x + hv.y * w3.y + hv.z * w3.z + hv.w * w3.w;
        }
        {
            float* pp = part + (kh * 32 + lane) * PART_STR + cg * 4;
            pp[0] = a0; pp[1] = a1; pp[2] = a2; pp[3] = a3;
        }
        __syncthreads();

        if (t < 128) {
            const float* p0 = part + (0 * 32 + eb) * PART_STR + eu * 4;
            const float* p1 = part + (1 * 32 + eb) * PART_STR + eu * 4;
            float pi = p0[0] + p1[0] + xq0;
            float pf = p0[1] + p1[1] + xq1;
            float pg = p0[2] + p1[2] + xq2;
            float po = p0[3] + p1[3] + xq3;

            cc = sigmoidf_(pf) * cc + sigmoidf_(pi) * tanhf(pg);
            hh = sigmoidf_(po) * tanhf(cc);

            int gu = u0 + eu;
            g_h[(ts + 1) & 1][eb * HID + gu] = hh;
            size_t o = ((size_t)ts * BATCH + eb) * HID + gu;
            out[o]           = hh;   // output
            out[OFF_ALL + o] = hh;   // all_hidden_state
        }

        grid_barrier(lsense);
    }

    if (t < 128) {
        int gu = u0 + eu;
        out[OFF_HT + (size_t)eb * HID + gu] = hh;
        out[OFF_CT + (size_t)eb * HID + gu] = cc;
    }
}

// ---------------------------------------------------------------------------
extern "C" void kernel_launch(void* const* d_in, const int* in_sizes, int n_in,
                              void* d_out, int out_size) {
    const float* x  = (const float*)d_in[0];   // [T,B,I]
    const float* h0 = (const float*)d_in[1];   // [1,B,H]
    const float* c0 = (const float*)d_in[2];   // [1,B,H]
    const float* Wx = (const float*)d_in[3];   // [4H,I]
    const float* Wh = (const float*)d_in[4];   // [4H,H]
    const float* b  = (const float*)d_in[5];   // [4H]
    float* out = (float*)d_out;

    // Allow >48KB dynamic SMEM for the persistent kernel (host-side, idempotent)
    cudaFuncSetAttribute(lstm_kernel,
                         cudaFuncAttributeMaxDynamicSharedMemorySize, SMEM_BYTES);

    dim3 g1(G4 / 128, (T_STEPS * BATCH) / 64);   // (16, 512)
    pregemm_kernel<<<g1, TPB>>>(x, Wx, b);

    lstm_kernel<<<NCTA, TPB, SMEM_BYTES>>>(Wh, h0, c0, out);
}